// round 5
// baseline (speedup 1.0000x reference)
#include <cuda_runtime.h>

// Problem constants: N=100000, E=1600000, F=128, H=64, L=3
#define NMAX 100000
#define EMAX 1600000

// Scratch (device globals)
__device__ float g_bufY[NMAX * 64];   // y = h@Wa, later reused for h2
__device__ float g_bufZ[NMAX * 64];   // z = relu(agg_y + ba)
__device__ float g_hA[NMAX * 64];
__device__ float g_hB[NMAX * 64];
__device__ float g_stats[4 * 128];    // per-layer: [0..63] colsum, [64..127] colsumsq
__device__ int2  g_edges[EMAX];       // (src, w_bits) grouped by dst
__device__ int   g_deg[NMAX];
__device__ int   g_off[NMAX];
__device__ int   g_cur[NMAX];
__device__ int   g_total;
__device__ int   g_is32;

// ---------------------------------------------------------------------------
// CSR build
// ---------------------------------------------------------------------------
__global__ void k_prep(int* __restrict__ deg, float* __restrict__ stats, int N) {
    if (blockIdx.x == 0 && threadIdx.x == 0) { g_total = 0; g_is32 = 0; }
    if (blockIdx.x == 0 && threadIdx.x < 512) stats[threadIdx.x] = 0.0f;
    int stride = gridDim.x * blockDim.x;
    for (int i = blockIdx.x * blockDim.x + threadIdx.x; i < N; i += stride)
        deg[i] = 0;
}

__global__ void k_detect(const int* __restrict__ ei, int E) {
    int stride = gridDim.x * blockDim.x;
    for (int j = blockIdx.x * blockDim.x + threadIdx.x; j < E; j += stride) {
        if (ei[2 * j + 1] != 0) { g_is32 = 1; return; }
    }
}

__global__ void k_hist(const void* __restrict__ ei, int* __restrict__ deg, int E) {
    int is32 = g_is32;
    int stride = gridDim.x * blockDim.x;
    for (int i = blockIdx.x * blockDim.x + threadIdx.x; i < E; i += stride) {
        int d = is32 ? ((const int*)ei)[E + i] : (int)((const long long*)ei)[E + i];
        atomicAdd(&deg[d], 1);
    }
}

__global__ void k_alloc(const int* __restrict__ deg, int* __restrict__ off,
                        int* __restrict__ cur, int N) {
    int stride = gridDim.x * blockDim.x;
    for (int i = blockIdx.x * blockDim.x + threadIdx.x; i < N; i += stride) {
        int o = atomicAdd(&g_total, deg[i]);
        off[i] = o;
        cur[i] = o;
    }
}

__global__ void k_fill(const void* __restrict__ ei, const float* __restrict__ ew,
                       int* __restrict__ cur, int2* __restrict__ edges, int E) {
    int is32 = g_is32;
    int stride = gridDim.x * blockDim.x;
    for (int i = blockIdx.x * blockDim.x + threadIdx.x; i < E; i += stride) {
        int s, d;
        if (is32) {
            const int* e = (const int*)ei;
            s = e[i]; d = e[E + i];
        } else {
            const long long* e = (const long long*)ei;
            s = (int)e[i]; d = (int)e[E + i];
        }
        int pos = atomicAdd(&cur[d], 1);
        edges[pos] = make_int2(s, __float_as_int(ew[i]));
    }
}

// ---------------------------------------------------------------------------
// Tiled dense GEMM: out[N,64] = in[N,FIN] @ W[FIN,64] (+ bias) (+ BN stats)
// Block: 256 threads, tile 64 nodes. Thread tile 4 nodes x 4 cols.
// ---------------------------------------------------------------------------
template <int FIN, bool STATS>
__global__ __launch_bounds__(256)
void k_gemm(const float* __restrict__ in, const float* __restrict__ W,
            const float* __restrict__ bias, float* __restrict__ out,
            float* __restrict__ stats, int N) {
    constexpr int P = FIN + 4;        // padded input row stride (float4-aligned)
    extern __shared__ float sm[];
    float* sW    = sm;                // FIN*64
    float* sIn   = sW + FIN * 64;     // 64*P
    float* sstat = sIn + 64 * P;      // 128

    int tid = threadIdx.x;
    int n0 = blockIdx.x * 64;

    for (int i = tid; i < FIN * 16; i += 256)
        ((float4*)sW)[i] = ((const float4*)W)[i];

    constexpr int KQ = FIN / 4;
    for (int i = tid; i < 64 * KQ; i += 256) {
        int node = i / KQ, kq = i % KQ;
        int row = n0 + node;
        float4 v = (row < N) ? ((const float4*)(in + (size_t)row * FIN))[kq]
                             : make_float4(0.f, 0.f, 0.f, 0.f);
        ((float4*)(sIn + node * P))[kq] = v;
    }
    if (STATS && tid < 128) sstat[tid] = 0.0f;
    __syncthreads();

    int tx = tid & 15, ty = tid >> 4;
    float acc[4][4];
    #pragma unroll
    for (int i = 0; i < 4; i++)
        #pragma unroll
        for (int j = 0; j < 4; j++) acc[i][j] = 0.0f;

    const float* a0p = sIn + (4 * ty + 0) * P;
    const float* a1p = sIn + (4 * ty + 1) * P;
    const float* a2p = sIn + (4 * ty + 2) * P;
    const float* a3p = sIn + (4 * ty + 3) * P;

    #pragma unroll 4
    for (int k = 0; k < FIN; k++) {
        float4 b = *(const float4*)(sW + k * 64 + 4 * tx);
        float a0 = a0p[k], a1 = a1p[k], a2 = a2p[k], a3 = a3p[k];
        acc[0][0] += a0 * b.x; acc[0][1] += a0 * b.y; acc[0][2] += a0 * b.z; acc[0][3] += a0 * b.w;
        acc[1][0] += a1 * b.x; acc[1][1] += a1 * b.y; acc[1][2] += a1 * b.z; acc[1][3] += a1 * b.w;
        acc[2][0] += a2 * b.x; acc[2][1] += a2 * b.y; acc[2][2] += a2 * b.z; acc[2][3] += a2 * b.w;
        acc[3][0] += a3 * b.x; acc[3][1] += a3 * b.y; acc[3][2] += a3 * b.z; acc[3][3] += a3 * b.w;
    }

    float bx = 0.f, by = 0.f, bz = 0.f, bw = 0.f;
    if (bias) {
        float4 bv = *(const float4*)(bias + 4 * tx);
        bx = bv.x; by = bv.y; bz = bv.z; bw = bv.w;
    }

    float s[4] = {0.f, 0.f, 0.f, 0.f};
    float q[4] = {0.f, 0.f, 0.f, 0.f};
    #pragma unroll
    for (int i = 0; i < 4; i++) {
        int row = n0 + 4 * ty + i;
        if (row < N) {
            float4 r = make_float4(acc[i][0] + bx, acc[i][1] + by,
                                   acc[i][2] + bz, acc[i][3] + bw);
            *(float4*)(out + (size_t)row * 64 + 4 * tx) = r;
            if (STATS) {
                s[0] += r.x; q[0] += r.x * r.x;
                s[1] += r.y; q[1] += r.y * r.y;
                s[2] += r.z; q[2] += r.z * r.z;
                s[3] += r.w; q[3] += r.w * r.w;
            }
        }
    }

    if (STATS) {
        #pragma unroll
        for (int j = 0; j < 4; j++) {
            atomicAdd(&sstat[4 * tx + j], s[j]);
            atomicAdd(&sstat[64 + 4 * tx + j], q[j]);
        }
        __syncthreads();
        if (tid < 128) atomicAdd(&stats[tid], sstat[tid]);
    }
}

// ---------------------------------------------------------------------------
// Gather (post-transform): z[n] = relu((1+eps)*y[n] + sum_e w_e*y[src_e] + ba)
// HALF-WARP per node: 16 lanes x float4 cover the 64-float row with LDG.128.
// Edge batches of 16 match mean degree; 8-deep unroll for MLP.
// ---------------------------------------------------------------------------
__global__ __launch_bounds__(256)
void k_gath(const float* __restrict__ y, const int* __restrict__ off,
            const int* __restrict__ deg, const int2* __restrict__ edges,
            const float* __restrict__ epsp, const float* __restrict__ ba,
            float* __restrict__ z, int N) {
    int hw   = (blockIdx.x * blockDim.x + threadIdx.x) >> 4;
    int lane = threadIdx.x & 15;
    int nhw  = (gridDim.x * blockDim.x) >> 4;
    float c = 1.0f + *epsp;
    float4 bias = ((const float4*)ba)[lane];

    for (int n = hw; n < N; n += nhw) {
        int o = off[n];
        int d = deg[n];

        float4 a = ((const float4*)(y + (size_t)n * 64))[lane];
        a.x *= c; a.y *= c; a.z *= c; a.w *= c;

        for (int e0 = 0; e0 < d; e0 += 16) {
            int cnt = min(16, d - e0);
            int2 ed = (lane < cnt) ? edges[o + e0 + lane] : make_int2(0, 0);
            int j = 0;
            for (; j + 8 <= cnt; j += 8) {
                int si[8]; float wi[8];
                #pragma unroll
                for (int u = 0; u < 8; u++) {
                    si[u] = __shfl_sync(0xffffffffu, ed.x, j + u, 16);
                    wi[u] = __int_as_float(__shfl_sync(0xffffffffu, ed.y, j + u, 16));
                }
                float4 v[8];
                #pragma unroll
                for (int u = 0; u < 8; u++)
                    v[u] = ((const float4*)(y + (size_t)si[u] * 64))[lane];
                #pragma unroll
                for (int u = 0; u < 8; u++) {
                    a.x += wi[u] * v[u].x;
                    a.y += wi[u] * v[u].y;
                    a.z += wi[u] * v[u].z;
                    a.w += wi[u] * v[u].w;
                }
            }
            for (; j < cnt; j++) {
                int   s = __shfl_sync(0xffffffffu, ed.x, j, 16);
                float w = __int_as_float(__shfl_sync(0xffffffffu, ed.y, j, 16));
                float4 v = ((const float4*)(y + (size_t)s * 64))[lane];
                a.x += w * v.x; a.y += w * v.y; a.z += w * v.z; a.w += w * v.w;
            }
        }

        float4 r = make_float4(fmaxf(a.x + bias.x, 0.0f), fmaxf(a.y + bias.y, 0.0f),
                               fmaxf(a.z + bias.z, 0.0f), fmaxf(a.w + bias.w, 0.0f));
        ((float4*)(z + (size_t)n * 64))[lane] = r;
    }
}

// ---------------------------------------------------------------------------
// BN apply + ReLU + optional residual
// ---------------------------------------------------------------------------
__global__ void k_bn(const float4* __restrict__ h2, const float* __restrict__ stats,
                     const float* __restrict__ g, const float* __restrict__ be,
                     const float4* __restrict__ prev, float4* __restrict__ out,
                     int total4, float invN) {
    __shared__ float sscale[64], sshift[64];
    int tid = threadIdx.x;
    if (tid < 64) {
        float m = stats[tid] * invN;
        float v = stats[64 + tid] * invN - m * m;
        float sc = g[tid] * rsqrtf(v + 1e-5f);
        sscale[tid] = sc;
        sshift[tid] = be[tid] - m * sc;
    }
    __syncthreads();
    int stride = gridDim.x * blockDim.x;
    for (int i = blockIdx.x * blockDim.x + tid; i < total4; i += stride) {
        int c = (i * 4) & 63;
        float4 h = h2[i];
        float4 r;
        r.x = fmaxf(h.x * sscale[c + 0] + sshift[c + 0], 0.0f);
        r.y = fmaxf(h.y * sscale[c + 1] + sshift[c + 1], 0.0f);
        r.z = fmaxf(h.z * sscale[c + 2] + sshift[c + 2], 0.0f);
        r.w = fmaxf(h.w * sscale[c + 3] + sshift[c + 3], 0.0f);
        if (prev) {
            float4 p = prev[i];
            r.x += p.x; r.y += p.y; r.z += p.z; r.w += p.w;
        }
        out[i] = r;
    }
}

// ---------------------------------------------------------------------------
extern "C" void kernel_launch(void* const* d_in, const int* in_sizes, int n_in,
                              void* d_out, int out_size) {
    const float* x    = (const float*)d_in[0];
    const void*  ei   = d_in[1];
    const float* ew   = (const float*)d_in[2];
    const float* eps1 = (const float*)d_in[3];
    const float* W1a  = (const float*)d_in[4];
    const float* b1a  = (const float*)d_in[5];
    const float* W1b  = (const float*)d_in[6];
    const float* b1b  = (const float*)d_in[7];
    const float* g1   = (const float*)d_in[8];
    const float* be1  = (const float*)d_in[9];
    const float* epss = (const float*)d_in[10];
    const float* Wsa  = (const float*)d_in[11];
    const float* bsa  = (const float*)d_in[12];
    const float* Wsb  = (const float*)d_in[13];
    const float* bsb  = (const float*)d_in[14];
    const float* gs   = (const float*)d_in[15];
    const float* bes  = (const float*)d_in[16];

    int N   = in_sizes[0] / 128;
    int E   = in_sizes[2];
    int Lm1 = in_sizes[10];

    float *bufY, *bufZ, *hA, *hB, *stats;
    int *deg, *off, *cur;
    int2* edges;
    cudaGetSymbolAddress((void**)&bufY,  g_bufY);
    cudaGetSymbolAddress((void**)&bufZ,  g_bufZ);
    cudaGetSymbolAddress((void**)&hA,    g_hA);
    cudaGetSymbolAddress((void**)&hB,    g_hB);
    cudaGetSymbolAddress((void**)&stats, g_stats);
    cudaGetSymbolAddress((void**)&deg,   g_deg);
    cudaGetSymbolAddress((void**)&off,   g_off);
    cudaGetSymbolAddress((void**)&cur,   g_cur);
    cudaGetSymbolAddress((void**)&edges, g_edges);

    const size_t shg128 = (size_t)(128 * 64 + 64 * (128 + 4) + 128) * 4;
    const size_t shg64  = (size_t)(64 * 64 + 64 * (64 + 4) + 128) * 4;
    cudaFuncSetAttribute(k_gemm<128, false>, cudaFuncAttributeMaxDynamicSharedMemorySize, (int)shg128);
    cudaFuncSetAttribute(k_gemm<64, false>,  cudaFuncAttributeMaxDynamicSharedMemorySize, (int)shg64);
    cudaFuncSetAttribute(k_gemm<64, true>,   cudaFuncAttributeMaxDynamicSharedMemorySize, (int)shg64);

    float invN = 1.0f / (float)N;
    int gemmBlocks = (N + 63) / 64;
    int gathBlocks = 148 * 8;
    int bnBlocks   = (N * 16 + 255) / 256;

    // ---- CSR build; layer-1 GEMM hoisted to slot 3 (independent of CSR) ----
    k_prep<<<(N + 255) / 256, 512>>>(deg, stats, N);
    k_detect<<<512, 256>>>((const int*)ei, E);
    k_hist<<<1024, 256>>>(ei, deg, E);
    k_gemm<128, false><<<gemmBlocks, 256, shg128>>>(x, W1a, nullptr, bufY, nullptr, N);
    k_alloc<<<(N + 255) / 256, 256>>>(deg, off, cur, N);
    k_fill<<<1024, 256>>>(ei, ew, cur, edges, E);

    // ---- layer 1 (F=128 -> H=64) ----
    k_gath<<<gathBlocks, 256>>>(bufY, off, deg, edges, eps1, b1a, bufZ, N);
    k_gemm<64, true><<<gemmBlocks, 256, shg64>>>(bufZ, W1b, b1b, bufY, stats, N);
    k_bn<<<bnBlocks, 256>>>((const float4*)bufY, stats, g1, be1, nullptr, (float4*)hA,
                            N * 16, invN);

    // ---- layers 2..L (H=64 -> H=64, residual) ----
    const float* curh = hA;
    for (int i = 0; i < Lm1; i++) {
        float* outp = (i == Lm1 - 1) ? (float*)d_out : ((curh == hA) ? hB : hA);
        float* lstats = stats + (size_t)(i + 1) * 128;
        k_gemm<64, false><<<gemmBlocks, 256, shg64>>>(curh, Wsa + (size_t)i * 64 * 64,
                                                      nullptr, bufY, nullptr, N);
        k_gath<<<gathBlocks, 256>>>(bufY, off, deg, edges, epss + i, bsa + i * 64,
                                    bufZ, N);
        k_gemm<64, true><<<gemmBlocks, 256, shg64>>>(bufZ, Wsb + (size_t)i * 64 * 64,
                                                     bsb + i * 64, bufY, lstats, N);
        k_bn<<<bnBlocks, 256>>>((const float4*)bufY, lstats, gs + i * 64, bes + i * 64,
                                (const float4*)curh, (float4*)outp, N * 16, invN);
        curh = outp;
    }
}

// round 6
// speedup vs baseline: 1.0002x; 1.0002x over previous
#include <cuda_runtime.h>

// Problem constants: N=100000, E=1600000, F=128, H=64, L=3
#define NMAX 100000
#define EMAX 1600000

// Scratch (device globals)
__device__ float g_bufY[NMAX * 64];   // y = h@Wa, later reused for h2
__device__ float g_bufZ[NMAX * 64];   // z = relu(agg_y + ba)
__device__ float g_hA[NMAX * 64];
__device__ float g_hB[NMAX * 64];
__device__ float g_stats[4 * 128];    // per-layer: [0..63] colsum, [64..127] colsumsq
__device__ int2  g_edges[EMAX];       // (src, w_bits) grouped by dst
__device__ int   g_deg[NMAX];
__device__ int   g_off[NMAX];
__device__ int   g_cur[NMAX];
__device__ int   g_total;
__device__ int   g_is32;

// ---------------------------------------------------------------------------
// CSR build
// ---------------------------------------------------------------------------
__global__ void k_prep(int* __restrict__ deg, float* __restrict__ stats, int N) {
    if (blockIdx.x == 0 && threadIdx.x == 0) { g_total = 0; g_is32 = 0; }
    if (blockIdx.x == 0 && threadIdx.x < 512) stats[threadIdx.x] = 0.0f;
    int stride = gridDim.x * blockDim.x;
    for (int i = blockIdx.x * blockDim.x + threadIdx.x; i < N; i += stride)
        deg[i] = 0;
}

__global__ void k_detect(const int* __restrict__ ei, int E) {
    int stride = gridDim.x * blockDim.x;
    for (int j = blockIdx.x * blockDim.x + threadIdx.x; j < E; j += stride) {
        if (ei[2 * j + 1] != 0) { g_is32 = 1; return; }
    }
}

__global__ void k_hist(const void* __restrict__ ei, int* __restrict__ deg, int E) {
    int is32 = g_is32;
    int stride = gridDim.x * blockDim.x;
    for (int i = blockIdx.x * blockDim.x + threadIdx.x; i < E; i += stride) {
        int d = is32 ? ((const int*)ei)[E + i] : (int)((const long long*)ei)[E + i];
        atomicAdd(&deg[d], 1);
    }
}

__global__ void k_alloc(const int* __restrict__ deg, int* __restrict__ off,
                        int* __restrict__ cur, int N) {
    int stride = gridDim.x * blockDim.x;
    for (int i = blockIdx.x * blockDim.x + threadIdx.x; i < N; i += stride) {
        int o = atomicAdd(&g_total, deg[i]);
        off[i] = o;
        cur[i] = o;
    }
}

__global__ void k_fill(const void* __restrict__ ei, const float* __restrict__ ew,
                       int* __restrict__ cur, int2* __restrict__ edges, int E) {
    int is32 = g_is32;
    int stride = gridDim.x * blockDim.x;
    for (int i = blockIdx.x * blockDim.x + threadIdx.x; i < E; i += stride) {
        int s, d;
        if (is32) {
            const int* e = (const int*)ei;
            s = e[i]; d = e[E + i];
        } else {
            const long long* e = (const long long*)ei;
            s = (int)e[i]; d = (int)e[E + i];
        }
        int pos = atomicAdd(&cur[d], 1);
        edges[pos] = make_int2(s, __float_as_int(ew[i]));
    }
}

// ---------------------------------------------------------------------------
// Tiled dense GEMM: out[N,64] = in[N,FIN] @ W[FIN,64] (+ bias) (+ BN stats)
// Block: 256 threads, tile 64 nodes. Thread tile 4 nodes x 4 cols.
// ---------------------------------------------------------------------------
template <int FIN, bool STATS>
__global__ __launch_bounds__(256)
void k_gemm(const float* __restrict__ in, const float* __restrict__ W,
            const float* __restrict__ bias, float* __restrict__ out,
            float* __restrict__ stats, int N) {
    constexpr int P = FIN + 4;        // padded input row stride (float4-aligned)
    extern __shared__ float sm[];
    float* sW    = sm;                // FIN*64
    float* sIn   = sW + FIN * 64;     // 64*P
    float* sstat = sIn + 64 * P;      // 128

    int tid = threadIdx.x;
    int n0 = blockIdx.x * 64;

    for (int i = tid; i < FIN * 16; i += 256)
        ((float4*)sW)[i] = ((const float4*)W)[i];

    constexpr int KQ = FIN / 4;
    for (int i = tid; i < 64 * KQ; i += 256) {
        int node = i / KQ, kq = i % KQ;
        int row = n0 + node;
        float4 v = (row < N) ? ((const float4*)(in + (size_t)row * FIN))[kq]
                             : make_float4(0.f, 0.f, 0.f, 0.f);
        ((float4*)(sIn + node * P))[kq] = v;
    }
    if (STATS && tid < 128) sstat[tid] = 0.0f;
    __syncthreads();

    int tx = tid & 15, ty = tid >> 4;
    float acc[4][4];
    #pragma unroll
    for (int i = 0; i < 4; i++)
        #pragma unroll
        for (int j = 0; j < 4; j++) acc[i][j] = 0.0f;

    const float* a0p = sIn + (4 * ty + 0) * P;
    const float* a1p = sIn + (4 * ty + 1) * P;
    const float* a2p = sIn + (4 * ty + 2) * P;
    const float* a3p = sIn + (4 * ty + 3) * P;

    #pragma unroll 4
    for (int k = 0; k < FIN; k++) {
        float4 b = *(const float4*)(sW + k * 64 + 4 * tx);
        float a0 = a0p[k], a1 = a1p[k], a2 = a2p[k], a3 = a3p[k];
        acc[0][0] += a0 * b.x; acc[0][1] += a0 * b.y; acc[0][2] += a0 * b.z; acc[0][3] += a0 * b.w;
        acc[1][0] += a1 * b.x; acc[1][1] += a1 * b.y; acc[1][2] += a1 * b.z; acc[1][3] += a1 * b.w;
        acc[2][0] += a2 * b.x; acc[2][1] += a2 * b.y; acc[2][2] += a2 * b.z; acc[2][3] += a2 * b.w;
        acc[3][0] += a3 * b.x; acc[3][1] += a3 * b.y; acc[3][2] += a3 * b.z; acc[3][3] += a3 * b.w;
    }

    float bx = 0.f, by = 0.f, bz = 0.f, bw = 0.f;
    if (bias) {
        float4 bv = *(const float4*)(bias + 4 * tx);
        bx = bv.x; by = bv.y; bz = bv.z; bw = bv.w;
    }

    float s[4] = {0.f, 0.f, 0.f, 0.f};
    float q[4] = {0.f, 0.f, 0.f, 0.f};
    #pragma unroll
    for (int i = 0; i < 4; i++) {
        int row = n0 + 4 * ty + i;
        if (row < N) {
            float4 r = make_float4(acc[i][0] + bx, acc[i][1] + by,
                                   acc[i][2] + bz, acc[i][3] + bw);
            *(float4*)(out + (size_t)row * 64 + 4 * tx) = r;
            if (STATS) {
                s[0] += r.x; q[0] += r.x * r.x;
                s[1] += r.y; q[1] += r.y * r.y;
                s[2] += r.z; q[2] += r.z * r.z;
                s[3] += r.w; q[3] += r.w * r.w;
            }
        }
    }

    if (STATS) {
        #pragma unroll
        for (int j = 0; j < 4; j++) {
            atomicAdd(&sstat[4 * tx + j], s[j]);
            atomicAdd(&sstat[64 + 4 * tx + j], q[j]);
        }
        __syncthreads();
        if (tid < 128) atomicAdd(&stats[tid], sstat[tid]);
    }
}

// ---------------------------------------------------------------------------
// Gather (post-transform): z[n] = relu((1+eps)*y[n] + sum_e w_e*y[src_e] + ba)
// HALF-WARP per node: 16 lanes x float4 cover the 64-float row with LDG.128.
// Edge batches of 16 match mean degree; 8-deep unroll for MLP.
// ---------------------------------------------------------------------------
__global__ __launch_bounds__(256)
void k_gath(const float* __restrict__ y, const int* __restrict__ off,
            const int* __restrict__ deg, const int2* __restrict__ edges,
            const float* __restrict__ epsp, const float* __restrict__ ba,
            float* __restrict__ z, int N) {
    int hw   = (blockIdx.x * blockDim.x + threadIdx.x) >> 4;
    int lane = threadIdx.x & 15;
    int nhw  = (gridDim.x * blockDim.x) >> 4;
    float c = 1.0f + *epsp;
    float4 bias = ((const float4*)ba)[lane];

    for (int n = hw; n < N; n += nhw) {
        int o = off[n];
        int d = deg[n];

        float4 a = ((const float4*)(y + (size_t)n * 64))[lane];
        a.x *= c; a.y *= c; a.z *= c; a.w *= c;

        for (int e0 = 0; e0 < d; e0 += 16) {
            int cnt = min(16, d - e0);
            int2 ed = (lane < cnt) ? edges[o + e0 + lane] : make_int2(0, 0);
            int j = 0;
            for (; j + 8 <= cnt; j += 8) {
                int si[8]; float wi[8];
                #pragma unroll
                for (int u = 0; u < 8; u++) {
                    si[u] = __shfl_sync(0xffffffffu, ed.x, j + u, 16);
                    wi[u] = __int_as_float(__shfl_sync(0xffffffffu, ed.y, j + u, 16));
                }
                float4 v[8];
                #pragma unroll
                for (int u = 0; u < 8; u++)
                    v[u] = ((const float4*)(y + (size_t)si[u] * 64))[lane];
                #pragma unroll
                for (int u = 0; u < 8; u++) {
                    a.x += wi[u] * v[u].x;
                    a.y += wi[u] * v[u].y;
                    a.z += wi[u] * v[u].z;
                    a.w += wi[u] * v[u].w;
                }
            }
            for (; j < cnt; j++) {
                int   s = __shfl_sync(0xffffffffu, ed.x, j, 16);
                float w = __int_as_float(__shfl_sync(0xffffffffu, ed.y, j, 16));
                float4 v = ((const float4*)(y + (size_t)s * 64))[lane];
                a.x += w * v.x; a.y += w * v.y; a.z += w * v.z; a.w += w * v.w;
            }
        }

        float4 r = make_float4(fmaxf(a.x + bias.x, 0.0f), fmaxf(a.y + bias.y, 0.0f),
                               fmaxf(a.z + bias.z, 0.0f), fmaxf(a.w + bias.w, 0.0f));
        ((float4*)(z + (size_t)n * 64))[lane] = r;
    }
}

// ---------------------------------------------------------------------------
// BN apply + ReLU + optional residual
// ---------------------------------------------------------------------------
__global__ void k_bn(const float4* __restrict__ h2, const float* __restrict__ stats,
                     const float* __restrict__ g, const float* __restrict__ be,
                     const float4* __restrict__ prev, float4* __restrict__ out,
                     int total4, float invN) {
    __shared__ float sscale[64], sshift[64];
    int tid = threadIdx.x;
    if (tid < 64) {
        float m = stats[tid] * invN;
        float v = stats[64 + tid] * invN - m * m;
        float sc = g[tid] * rsqrtf(v + 1e-5f);
        sscale[tid] = sc;
        sshift[tid] = be[tid] - m * sc;
    }
    __syncthreads();
    int stride = gridDim.x * blockDim.x;
    for (int i = blockIdx.x * blockDim.x + tid; i < total4; i += stride) {
        int c = (i * 4) & 63;
        float4 h = h2[i];
        float4 r;
        r.x = fmaxf(h.x * sscale[c + 0] + sshift[c + 0], 0.0f);
        r.y = fmaxf(h.y * sscale[c + 1] + sshift[c + 1], 0.0f);
        r.z = fmaxf(h.z * sscale[c + 2] + sshift[c + 2], 0.0f);
        r.w = fmaxf(h.w * sscale[c + 3] + sshift[c + 3], 0.0f);
        if (prev) {
            float4 p = prev[i];
            r.x += p.x; r.y += p.y; r.z += p.z; r.w += p.w;
        }
        out[i] = r;
    }
}

// ---------------------------------------------------------------------------
extern "C" void kernel_launch(void* const* d_in, const int* in_sizes, int n_in,
                              void* d_out, int out_size) {
    const float* x    = (const float*)d_in[0];
    const void*  ei   = d_in[1];
    const float* ew   = (const float*)d_in[2];
    const float* eps1 = (const float*)d_in[3];
    const float* W1a  = (const float*)d_in[4];
    const float* b1a  = (const float*)d_in[5];
    const float* W1b  = (const float*)d_in[6];
    const float* b1b  = (const float*)d_in[7];
    const float* g1   = (const float*)d_in[8];
    const float* be1  = (const float*)d_in[9];
    const float* epss = (const float*)d_in[10];
    const float* Wsa  = (const float*)d_in[11];
    const float* bsa  = (const float*)d_in[12];
    const float* Wsb  = (const float*)d_in[13];
    const float* bsb  = (const float*)d_in[14];
    const float* gs   = (const float*)d_in[15];
    const float* bes  = (const float*)d_in[16];

    int N   = in_sizes[0] / 128;
    int E   = in_sizes[2];
    int Lm1 = in_sizes[10];

    float *bufY, *bufZ, *hA, *hB, *stats;
    int *deg, *off, *cur;
    int2* edges;
    cudaGetSymbolAddress((void**)&bufY,  g_bufY);
    cudaGetSymbolAddress((void**)&bufZ,  g_bufZ);
    cudaGetSymbolAddress((void**)&hA,    g_hA);
    cudaGetSymbolAddress((void**)&hB,    g_hB);
    cudaGetSymbolAddress((void**)&stats, g_stats);
    cudaGetSymbolAddress((void**)&deg,   g_deg);
    cudaGetSymbolAddress((void**)&off,   g_off);
    cudaGetSymbolAddress((void**)&cur,   g_cur);
    cudaGetSymbolAddress((void**)&edges, g_edges);

    const size_t shg128 = (size_t)(128 * 64 + 64 * (128 + 4) + 128) * 4;
    const size_t shg64  = (size_t)(64 * 64 + 64 * (64 + 4) + 128) * 4;
    cudaFuncSetAttribute(k_gemm<128, false>, cudaFuncAttributeMaxDynamicSharedMemorySize, (int)shg128);
    cudaFuncSetAttribute(k_gemm<64, false>,  cudaFuncAttributeMaxDynamicSharedMemorySize, (int)shg64);
    cudaFuncSetAttribute(k_gemm<64, true>,   cudaFuncAttributeMaxDynamicSharedMemorySize, (int)shg64);

    float invN = 1.0f / (float)N;
    int gemmBlocks = (N + 63) / 64;
    int gathBlocks = 148 * 8;
    int bnBlocks   = (N * 16 + 255) / 256;

    // ---- CSR build; layer-1 GEMM hoisted to slot 3 (independent of CSR) ----
    k_prep<<<(N + 255) / 256, 512>>>(deg, stats, N);
    k_detect<<<512, 256>>>((const int*)ei, E);
    k_hist<<<1024, 256>>>(ei, deg, E);
    k_gemm<128, false><<<gemmBlocks, 256, shg128>>>(x, W1a, nullptr, bufY, nullptr, N);
    k_alloc<<<(N + 255) / 256, 256>>>(deg, off, cur, N);
    k_fill<<<1024, 256>>>(ei, ew, cur, edges, E);

    // ---- layer 1 (F=128 -> H=64) ----
    k_gath<<<gathBlocks, 256>>>(bufY, off, deg, edges, eps1, b1a, bufZ, N);
    k_gemm<64, true><<<gemmBlocks, 256, shg64>>>(bufZ, W1b, b1b, bufY, stats, N);
    k_bn<<<bnBlocks, 256>>>((const float4*)bufY, stats, g1, be1, nullptr, (float4*)hA,
                            N * 16, invN);

    // ---- layers 2..L (H=64 -> H=64, residual) ----
    const float* curh = hA;
    for (int i = 0; i < Lm1; i++) {
        float* outp = (i == Lm1 - 1) ? (float*)d_out : ((curh == hA) ? hB : hA);
        float* lstats = stats + (size_t)(i + 1) * 128;
        k_gemm<64, false><<<gemmBlocks, 256, shg64>>>(curh, Wsa + (size_t)i * 64 * 64,
                                                      nullptr, bufY, nullptr, N);
        k_gath<<<gathBlocks, 256>>>(bufY, off, deg, edges, epss + i, bsa + i * 64,
                                    bufZ, N);
        k_gemm<64, true><<<gemmBlocks, 256, shg64>>>(bufZ, Wsb + (size_t)i * 64 * 64,
                                                     bsb + i * 64, bufY, lstats, N);
        k_bn<<<bnBlocks, 256>>>((const float4*)bufY, lstats, gs + i * 64, bes + i * 64,
                                (const float4*)curh, (float4*)outp, N * 16, invN);
        curh = outp;
    }
}

// round 9
// speedup vs baseline: 1.2369x; 1.2367x over previous
#include <cuda_runtime.h>

// Problem constants: N=100000, E=1600000, F=128, H=64, L=3
#define NMAX 100000
#define EMAX 1600000

// Scratch (device globals)
__device__ float g_bufY[NMAX * 64];   // y = h@Wa, later reused for h2
__device__ float g_bufZ[NMAX * 64];   // z = relu(agg_y + ba)
__device__ float g_hA[NMAX * 64];
__device__ float g_hB[NMAX * 64];
__device__ float g_stats[4 * 128];    // per-layer: [0..63] colsum, [64..127] colsumsq
__device__ int2  g_edges[EMAX];       // (src, w_bits) grouped by dst
__device__ int   g_deg[NMAX];
__device__ int   g_off[NMAX];
__device__ int   g_cur[NMAX];
__device__ int   g_total;
__device__ int   g_is32;

// ---------------------------------------------------------------------------
// CSR build
// ---------------------------------------------------------------------------
__global__ void k_prep(int* __restrict__ deg, float* __restrict__ stats, int N) {
    if (blockIdx.x == 0 && threadIdx.x == 0) { g_total = 0; g_is32 = 0; }
    if (blockIdx.x == 0 && threadIdx.x < 512) stats[threadIdx.x] = 0.0f;
    int stride = gridDim.x * blockDim.x;
    for (int i = blockIdx.x * blockDim.x + threadIdx.x; i < N; i += stride)
        deg[i] = 0;
}

__global__ void k_detect(const int* __restrict__ ei, int E) {
    int stride = gridDim.x * blockDim.x;
    for (int j = blockIdx.x * blockDim.x + threadIdx.x; j < E; j += stride) {
        if (ei[2 * j + 1] != 0) { g_is32 = 1; return; }
    }
}

__global__ void k_hist(const void* __restrict__ ei, int* __restrict__ deg, int E) {
    int is32 = g_is32;
    int stride = gridDim.x * blockDim.x;
    for (int i = blockIdx.x * blockDim.x + threadIdx.x; i < E; i += stride) {
        int d = is32 ? ((const int*)ei)[E + i] : (int)((const long long*)ei)[E + i];
        atomicAdd(&deg[d], 1);
    }
}

__global__ void k_alloc(const int* __restrict__ deg, int* __restrict__ off,
                        int* __restrict__ cur, int N) {
    int stride = gridDim.x * blockDim.x;
    for (int i = blockIdx.x * blockDim.x + threadIdx.x; i < N; i += stride) {
        int o = atomicAdd(&g_total, deg[i]);
        off[i] = o;
        cur[i] = o;
    }
}

__global__ void k_fill(const void* __restrict__ ei, const float* __restrict__ ew,
                       int* __restrict__ cur, int2* __restrict__ edges, int E) {
    int is32 = g_is32;
    int stride = gridDim.x * blockDim.x;
    for (int i = blockIdx.x * blockDim.x + threadIdx.x; i < E; i += stride) {
        int s, d;
        if (is32) {
            const int* e = (const int*)ei;
            s = e[i]; d = e[E + i];
        } else {
            const long long* e = (const long long*)ei;
            s = (int)e[i]; d = (int)e[E + i];
        }
        int pos = atomicAdd(&cur[d], 1);
        edges[pos] = make_int2(s, __float_as_int(ew[i]));
    }
}

// ---------------------------------------------------------------------------
// Tiled dense GEMM: out[N,64] = in[N,FIN] @ W[FIN,64] (+ bias) (+ BN stats)
// Block: 256 threads, tile 64 nodes. Thread tile 4 nodes x 4 cols.
// Inner loop k-unrolled by 4 with float4 A-loads: 8 LDS.128 per 64 FMA.
// ---------------------------------------------------------------------------
template <int FIN, bool STATS>
__global__ __launch_bounds__(256)
void k_gemm(const float* __restrict__ in, const float* __restrict__ W,
            const float* __restrict__ bias, float* __restrict__ out,
            float* __restrict__ stats, int N) {
    constexpr int P = FIN + 4;        // padded input row stride (float4-aligned)
    extern __shared__ float sm[];
    float* sW    = sm;                // FIN*64
    float* sIn   = sW + FIN * 64;     // 64*P
    float* sstat = sIn + 64 * P;      // 128

    int tid = threadIdx.x;
    int n0 = blockIdx.x * 64;

    for (int i = tid; i < FIN * 16; i += 256)
        ((float4*)sW)[i] = ((const float4*)W)[i];

    constexpr int KQ = FIN / 4;
    for (int i = tid; i < 64 * KQ; i += 256) {
        int node = i / KQ, kq = i % KQ;
        int row = n0 + node;
        float4 v = (row < N) ? ((const float4*)(in + (size_t)row * FIN))[kq]
                             : make_float4(0.f, 0.f, 0.f, 0.f);
        ((float4*)(sIn + node * P))[kq] = v;
    }
    if (STATS && tid < 128) sstat[tid] = 0.0f;
    __syncthreads();

    int tx = tid & 15, ty = tid >> 4;
    float acc[4][4];
    #pragma unroll
    for (int i = 0; i < 4; i++)
        #pragma unroll
        for (int j = 0; j < 4; j++) acc[i][j] = 0.0f;

    const float* aBase = sIn + 4 * ty * P;
    const float* bBase = sW + 4 * tx;

    #pragma unroll 2
    for (int k = 0; k < FIN; k += 4) {
        float4 b0 = *(const float4*)(bBase + (k + 0) * 64);
        float4 b1 = *(const float4*)(bBase + (k + 1) * 64);
        float4 b2 = *(const float4*)(bBase + (k + 2) * 64);
        float4 b3 = *(const float4*)(bBase + (k + 3) * 64);
        #pragma unroll
        for (int i = 0; i < 4; i++) {
            float4 a = *(const float4*)(aBase + i * P + k);
            acc[i][0] += a.x * b0.x; acc[i][1] += a.x * b0.y;
            acc[i][2] += a.x * b0.z; acc[i][3] += a.x * b0.w;
            acc[i][0] += a.y * b1.x; acc[i][1] += a.y * b1.y;
            acc[i][2] += a.y * b1.z; acc[i][3] += a.y * b1.w;
            acc[i][0] += a.z * b2.x; acc[i][1] += a.z * b2.y;
            acc[i][2] += a.z * b2.z; acc[i][3] += a.z * b2.w;
            acc[i][0] += a.w * b3.x; acc[i][1] += a.w * b3.y;
            acc[i][2] += a.w * b3.z; acc[i][3] += a.w * b3.w;
        }
    }

    float bx = 0.f, by = 0.f, bz = 0.f, bw = 0.f;
    if (bias) {
        float4 bv = *(const float4*)(bias + 4 * tx);
        bx = bv.x; by = bv.y; bz = bv.z; bw = bv.w;
    }

    float s[4] = {0.f, 0.f, 0.f, 0.f};
    float q[4] = {0.f, 0.f, 0.f, 0.f};
    #pragma unroll
    for (int i = 0; i < 4; i++) {
        int row = n0 + 4 * ty + i;
        if (row < N) {
            float4 r = make_float4(acc[i][0] + bx, acc[i][1] + by,
                                   acc[i][2] + bz, acc[i][3] + bw);
            *(float4*)(out + (size_t)row * 64 + 4 * tx) = r;
            if (STATS) {
                s[0] += r.x; q[0] += r.x * r.x;
                s[1] += r.y; q[1] += r.y * r.y;
                s[2] += r.z; q[2] += r.z * r.z;
                s[3] += r.w; q[3] += r.w * r.w;
            }
        }
    }

    if (STATS) {
        #pragma unroll
        for (int j = 0; j < 4; j++) {
            atomicAdd(&sstat[4 * tx + j], s[j]);
            atomicAdd(&sstat[64 + 4 * tx + j], q[j]);
        }
        __syncthreads();
        if (tid < 128) atomicAdd(&stats[tid], sstat[tid]);
    }
}

// ---------------------------------------------------------------------------
// Gather (post-transform): z[n] = relu((1+eps)*y[n] + sum_e w_e*y[src_e] + ba)
// Warp per node (R4 proven shape); float2 per lane; 8-deep edge unroll.
// ---------------------------------------------------------------------------
__global__ __launch_bounds__(256)
void k_gath(const float* __restrict__ y, const int* __restrict__ off,
            const int* __restrict__ deg, const int2* __restrict__ edges,
            const float* __restrict__ epsp, const float* __restrict__ ba,
            float* __restrict__ z, int N) {
    int warp = (blockIdx.x * blockDim.x + threadIdx.x) >> 5;
    int lane = threadIdx.x & 31;
    int nwarps = (gridDim.x * blockDim.x) >> 5;
    float c = 1.0f + *epsp;
    float2 bias = ((const float2*)ba)[lane];

    for (int n = warp; n < N; n += nwarps) {
        int o = off[n];
        int d = deg[n];

        float2 a = ((const float2*)(y + (size_t)n * 64))[lane];
        a.x *= c; a.y *= c;

        for (int e0 = 0; e0 < d; e0 += 32) {
            int cnt = min(32, d - e0);
            int2 ed = (lane < cnt) ? edges[o + e0 + lane] : make_int2(0, 0);
            int j = 0;
            for (; j + 8 <= cnt; j += 8) {
                int si[8]; float wi[8];
                #pragma unroll
                for (int u = 0; u < 8; u++) {
                    si[u] = __shfl_sync(0xffffffffu, ed.x, j + u);
                    wi[u] = __int_as_float(__shfl_sync(0xffffffffu, ed.y, j + u));
                }
                float2 v[8];
                #pragma unroll
                for (int u = 0; u < 8; u++)
                    v[u] = ((const float2*)(y + (size_t)si[u] * 64))[lane];
                #pragma unroll
                for (int u = 0; u < 8; u++) {
                    a.x += wi[u] * v[u].x;
                    a.y += wi[u] * v[u].y;
                }
            }
            for (; j < cnt; j++) {
                int   s = __shfl_sync(0xffffffffu, ed.x, j);
                float w = __int_as_float(__shfl_sync(0xffffffffu, ed.y, j));
                float2 v = ((const float2*)(y + (size_t)s * 64))[lane];
                a.x += w * v.x;
                a.y += w * v.y;
            }
        }

        float2 r = make_float2(fmaxf(a.x + bias.x, 0.0f), fmaxf(a.y + bias.y, 0.0f));
        ((float2*)(z + (size_t)n * 64))[lane] = r;
    }
}

// ---------------------------------------------------------------------------
// BN apply + ReLU + optional residual
// ---------------------------------------------------------------------------
__global__ void k_bn(const float4* __restrict__ h2, const float* __restrict__ stats,
                     const float* __restrict__ g, const float* __restrict__ be,
                     const float4* __restrict__ prev, float4* __restrict__ out,
                     int total4, float invN) {
    __shared__ float sscale[64], sshift[64];
    int tid = threadIdx.x;
    if (tid < 64) {
        float m = stats[tid] * invN;
        float v = stats[64 + tid] * invN - m * m;
        float sc = g[tid] * rsqrtf(v + 1e-5f);
        sscale[tid] = sc;
        sshift[tid] = be[tid] - m * sc;
    }
    __syncthreads();
    int stride = gridDim.x * blockDim.x;
    for (int i = blockIdx.x * blockDim.x + tid; i < total4; i += stride) {
        int c = (i * 4) & 63;
        float4 h = h2[i];
        float4 r;
        r.x = fmaxf(h.x * sscale[c + 0] + sshift[c + 0], 0.0f);
        r.y = fmaxf(h.y * sscale[c + 1] + sshift[c + 1], 0.0f);
        r.z = fmaxf(h.z * sscale[c + 2] + sshift[c + 2], 0.0f);
        r.w = fmaxf(h.w * sscale[c + 3] + sshift[c + 3], 0.0f);
        if (prev) {
            float4 p = prev[i];
            r.x += p.x; r.y += p.y; r.z += p.z; r.w += p.w;
        }
        out[i] = r;
    }
}

// ---------------------------------------------------------------------------
extern "C" void kernel_launch(void* const* d_in, const int* in_sizes, int n_in,
                              void* d_out, int out_size) {
    const float* x    = (const float*)d_in[0];
    const void*  ei   = d_in[1];
    const float* ew   = (const float*)d_in[2];
    const float* eps1 = (const float*)d_in[3];
    const float* W1a  = (const float*)d_in[4];
    const float* b1a  = (const float*)d_in[5];
    const float* W1b  = (const float*)d_in[6];
    const float* b1b  = (const float*)d_in[7];
    const float* g1   = (const float*)d_in[8];
    const float* be1  = (const float*)d_in[9];
    const float* epss = (const float*)d_in[10];
    const float* Wsa  = (const float*)d_in[11];
    const float* bsa  = (const float*)d_in[12];
    const float* Wsb  = (const float*)d_in[13];
    const float* bsb  = (const float*)d_in[14];
    const float* gs   = (const float*)d_in[15];
    const float* bes  = (const float*)d_in[16];

    int N   = in_sizes[0] / 128;
    int E   = in_sizes[2];
    int Lm1 = in_sizes[10];

    float *bufY, *bufZ, *hA, *hB, *stats;
    int *deg, *off, *cur;
    int2* edges;
    cudaGetSymbolAddress((void**)&bufY,  g_bufY);
    cudaGetSymbolAddress((void**)&bufZ,  g_bufZ);
    cudaGetSymbolAddress((void**)&hA,    g_hA);
    cudaGetSymbolAddress((void**)&hB,    g_hB);
    cudaGetSymbolAddress((void**)&stats, g_stats);
    cudaGetSymbolAddress((void**)&deg,   g_deg);
    cudaGetSymbolAddress((void**)&off,   g_off);
    cudaGetSymbolAddress((void**)&cur,   g_cur);
    cudaGetSymbolAddress((void**)&edges, g_edges);

    const size_t shg128 = (size_t)(128 * 64 + 64 * (128 + 4) + 128) * 4;
    const size_t shg64  = (size_t)(64 * 64 + 64 * (64 + 4) + 128) * 4;
    cudaFuncSetAttribute(k_gemm<128, false>, cudaFuncAttributeMaxDynamicSharedMemorySize, (int)shg128);
    cudaFuncSetAttribute(k_gemm<64, false>,  cudaFuncAttributeMaxDynamicSharedMemorySize, (int)shg64);
    cudaFuncSetAttribute(k_gemm<64, true>,   cudaFuncAttributeMaxDynamicSharedMemorySize, (int)shg64);

    float invN = 1.0f / (float)N;
    int gemmBlocks = (N + 63) / 64;
    int gathBlocks = 148 * 8;
    int bnBlocks   = (N * 16 + 255) / 256;

    // ---- CSR build; layer-1 GEMM hoisted to slot 3 (independent of CSR) ----
    k_prep<<<(N + 255) / 256, 512>>>(deg, stats, N);
    k_detect<<<512, 256>>>((const int*)ei, E);
    k_hist<<<1024, 256>>>(ei, deg, E);
    k_gemm<128, false><<<gemmBlocks, 256, shg128>>>(x, W1a, nullptr, bufY, nullptr, N);
    k_alloc<<<(N + 255) / 256, 256>>>(deg, off, cur, N);
    k_fill<<<1024, 256>>>(ei, ew, cur, edges, E);

    // ---- layer 1 (F=128 -> H=64) ----
    k_gath<<<gathBlocks, 256>>>(bufY, off, deg, edges, eps1, b1a, bufZ, N);
    k_gemm<64, true><<<gemmBlocks, 256, shg64>>>(bufZ, W1b, b1b, bufY, stats, N);
    k_bn<<<bnBlocks, 256>>>((const float4*)bufY, stats, g1, be1, nullptr, (float4*)hA,
                            N * 16, invN);

    // ---- layers 2..L (H=64 -> H=64, residual) ----
    const float* curh = hA;
    for (int i = 0; i < Lm1; i++) {
        float* outp = (i == Lm1 - 1) ? (float*)d_out : ((curh == hA) ? hB : hA);
        float* lstats = stats + (size_t)(i + 1) * 128;
        k_gemm<64, false><<<gemmBlocks, 256, shg64>>>(curh, Wsa + (size_t)i * 64 * 64,
                                                      nullptr, bufY, nullptr, N);
        k_gath<<<gathBlocks, 256>>>(bufY, off, deg, edges, epss + i, bsa + i * 64,
                                    bufZ, N);
        k_gemm<64, true><<<gemmBlocks, 256, shg64>>>(bufZ, Wsb + (size_t)i * 64 * 64,
                                                     bsb + i * 64, bufY, lstats, N);
        k_bn<<<bnBlocks, 256>>>((const float4*)bufY, lstats, gs + i * 64, bes + i * 64,
                                (const float4*)curh, (float4*)outp, N * 16, invN);
        curh = outp;
    }
}